// round 15
// baseline (speedup 1.0000x reference)
#include <cuda_runtime.h>
#include <cstdint>
#include <math.h>

// ---------------- problem-scale device scratch (static, no allocation) ----------------
#define NMAX 40960
__device__ float4 g_p4[NMAX];      // x, y, z, |p|^2
__device__ int    g_anchors[8192];
__device__ double g_terms[8192];

#define KK 20
#define INFF __int_as_float(0x7f800000)
typedef unsigned long long ull;

// ---------------- prep: SoA float4 with precomputed |p|^2 ----------------
__global__ void prep_kernel(const float* __restrict__ pos, int N) {
    int j = blockIdx.x * blockDim.x + threadIdx.x;
    if (j < N) {
        float x = pos[3*j], y = pos[3*j+1], z = pos[3*j+2];
        float n2 = __fadd_rn(__fadd_rn(__fmul_rn(x,x), __fmul_rn(y,y)), __fmul_rn(z,z));
        g_p4[j] = make_float4(x, y, z, n2);
    }
}

// ---------------- FPS: 16-CTA cluster, 256 thr/CTA; batched candidate-cache --------
#define FCT  16
#define FTPB 256
#define NW   (FTPB/32)    // 8 warps
#define FTOT (FCT*FTPB)   // 4096 threads
#define FP   10           // ceil(40000/4096)
#define NPAIR (FP/2)
#define IMAXI 0x7fffffff

__device__ __forceinline__ unsigned fps_mapa(unsigned addr, unsigned rank) {
    unsigned r;
    asm("mapa.shared::cluster.u32 %0, %1, %2;" : "=r"(r) : "r"(addr), "r"(rank));
    return r;
}
__device__ __forceinline__ unsigned smem_u32_(const void* p) {
    return (unsigned)__cvta_generic_to_shared(p);
}
__device__ __forceinline__ void cluster_sync_() {
    asm volatile("barrier.cluster.arrive.aligned;\n\tbarrier.cluster.wait.aligned;" ::: "memory");
}
__device__ __forceinline__ ull pack2(float lo, float hi) {
    ull v; asm("mov.b64 %0, {%1, %2};" : "=l"(v) : "r"(__float_as_uint(lo)), "r"(__float_as_uint(hi)));
    return v;
}
__device__ __forceinline__ void unpack2(ull v, float &lo, float &hi) {
    unsigned a, b; asm("mov.b64 {%0, %1}, %2;" : "=r"(a), "=r"(b) : "l"(v));
    lo = __uint_as_float(a); hi = __uint_as_float(b);
}
__device__ __forceinline__ ull add2_(ull a, ull b) {
    ull d; asm("add.rn.f32x2 %0, %1, %2;" : "=l"(d) : "l"(a), "l"(b)); return d;
}
__device__ __forceinline__ ull mul2_(ull a, ull b) {
    ull d; asm("mul.rn.f32x2 %0, %1, %2;" : "=l"(d) : "l"(a), "l"(b)); return d;
}
__device__ __forceinline__ ull fma2_(ull a, ull b, ull c) {
    ull d; asm("fma.rn.f32x2 %0, %1, %2, %3;" : "=l"(d) : "l"(a), "l"(b), "l"(c)); return d;
}

__global__ void __launch_bounds__(FTPB,1)
fps_kernel(int N, int nA) {
    extern __shared__ float4 s_pts[];          // [FTPB*FP] point mirror (40 KB)
    __shared__ ull      s_wkey[NW*3];          // per-warp: k1,k2,kb  (tagged)
    __shared__ ull      s_ck  [2][64];         // cache keys: val32|enc16|0  (16 CTAs x 4)
    __shared__ ull      s_cxy [2][64];         // cache positions x,y
    __shared__ float    s_cz  [2][64];         // cache positions z
    __shared__ unsigned s_cb  [2][FCT];        // per-CTA bounds
    __shared__ ull      s_bar [2];             // mbarriers (count = FCT)

    int tid  = threadIdx.x;
    unsigned rank; asm("mov.u32 %0, %%cluster_ctarank;" : "=r"(rank));
    int gt   = (int)rank * FTPB + tid;
    int lane = tid & 31, wid = tid >> 5;

    if (tid == 0) {
        asm volatile("mbarrier.init.shared.b64 [%0], %1;" :: "r"(smem_u32_(&s_bar[0])), "r"(FCT) : "memory");
        asm volatile("mbarrier.init.shared.b64 [%0], %1;" :: "r"(smem_u32_(&s_bar[1])), "r"(FCT) : "memory");
    }
    if (tid < NW*3) s_wkey[tid] = 0ull;        // tag 0 != first batch tag 1

    // register-resident points (5 packed pairs) + min-distance array
    ull X2[NPAIR], Y2[NPAIR], Z2[NPAIR];
    float md[FP];
    bool has10 = (9*FTOT + gt) < N;

    float4 a0 = g_p4[0];
    float xs[FP], ys[FP], zs[FP];
    #pragma unroll
    for (int s = 0; s < FP; s++) {
        int gi = s*FTOT + gt;                  // < NMAX; pad reads zero-init tail
        float4 q = g_p4[gi];
        s_pts[tid*FP + s] = q;
        xs[s]=q.x; ys[s]=q.y; zs[s]=q.z;
        float dx=q.x-a0.x, dy=q.y-a0.y, dz=q.z-a0.z;
        float d = fmaf(dx,dx, fmaf(dy,dy, dz*dz));
        bool valid = (s < 9) || has10;
        md[s] = valid ? d : -1.0f;
    }
    #pragma unroll
    for (int p = 0; p < NPAIR; p++) {
        X2[p] = pack2(xs[2*p], xs[2*p+1]);
        Y2[p] = pack2(ys[2*p], ys[2*p+1]);
        Z2[p] = pack2(zs[2*p], zs[2*p+1]);
    }
    if (rank == 0 && tid == 0) g_anchors[0] = 0;
    __syncthreads();      // s_pts, s_wkey, bars ready (CTA-local)
    cluster_sync_();      // visible cluster-wide before any remote store

    unsigned wkbase = smem_u32_(&s_wkey[0]);
    unsigned loc0   = smem_u32_(&s_ck[0][0]);
    int ph0 = 0, ph1 = 0;
    int m = 1;
    unsigned eb = 0;

    while (m < nA) {
        eb++;
        int buf = (int)(eb & 1u);
        unsigned tag = eb & 0xFFFFu;

        // ---- per-thread top-3 values + index recovery for top-2 ----
        float b1=-1.0f, b2=-1.0f, b3=-1.0f;
        #pragma unroll
        for (int s = 0; s < FP; s++) {
            float v = md[s];
            float t2 = fminf(b1, v); b1 = fmaxf(b1, v);
            float t3 = fminf(b2, t2); b2 = fmaxf(b2, t2);
            b3 = fmaxf(b3, t3);
        }
        int i1 = IMAXI, i2 = IMAXI;
        bool dup = (b2 == b1);
        #pragma unroll
        for (int s = 0; s < FP; s++) {
            float v = md[s]; int gi = gt + s*FTOT;
            if (v == b1) { if (i1 == IMAXI) i1 = gi; else if (dup && i2 == IMAXI) i2 = gi; }
            else if (!dup && v == b2) { if (i2 == IMAXI) i2 = gi; }
        }

        // ---- warp top-2 + 3rd-value bound (exact) ----
        unsigned v1b = __float_as_uint(b1);
        unsigned wv1 = __reduce_max_sync(0xFFFFFFFFu, v1b);
        unsigned e1  = 0xFFFFu - (unsigned)i1;
        unsigned cnd = (v1b == wv1) ? e1 : 0u;
        unsigned we1 = __reduce_max_sync(0xFFFFFFFFu, cnd);      // max enc = min idx
        bool A = (v1b == wv1) && (e1 == we1);
        unsigned cv2 = A ? __float_as_uint(b2) : v1b;
        unsigned ce2 = A ? (0xFFFFu - (unsigned)i2) : e1;
        unsigned wv2 = __reduce_max_sync(0xFFFFFFFFu, cv2);
        cnd = (cv2 == wv2) ? ce2 : 0u;
        unsigned we2 = __reduce_max_sync(0xFFFFFFFFu, cnd);
        bool B = (cv2 == wv2) && (ce2 == we2);
        unsigned cv3 = (A && B) ? __float_as_uint(b3)
                     : ((A || B) ? __float_as_uint(b2) : v1b);
        unsigned w3  = __reduce_max_sync(0xFFFFFFFFu, cv3);
        if (lane == 0) {
            ull k1 = ((ull)wv1 << 32) | ((ull)we1 << 16) | (ull)tag;
            ull k2 = ((ull)wv2 << 32) | ((ull)we2 << 16) | (ull)tag;
            ull kb = ((ull)w3  << 32) | (ull)tag;
            asm volatile("st.volatile.shared.u64 [%0], %1;" :: "r"(wkbase + (unsigned)((wid*3+0)*8)), "l"(k1) : "memory");
            asm volatile("st.volatile.shared.u64 [%0], %1;" :: "r"(wkbase + (unsigned)((wid*3+1)*8)), "l"(k2) : "memory");
            asm volatile("st.volatile.shared.u64 [%0], %1;" :: "r"(wkbase + (unsigned)((wid*3+2)*8)), "l"(kb) : "memory");
        }

        // ---- warp0: CTA top-4 of 16 warp keys + bound, ship to all 16 CTAs ----
        if (wid == 0) {
            ull myk = 0ull;
            if (lane < 2*NW) {
                unsigned a = wkbase + (unsigned)((((lane>>1)*3) + (lane&1))*8);
                do {
                    asm volatile("ld.volatile.shared.u64 %0, [%1];" : "=l"(myk) : "r"(a));
                } while ((unsigned)(myk & 0xFFFFull) != tag);
            }
            unsigned kbv = 0u;
            if (lane < NW) {
                ull kb_;
                unsigned a = wkbase + (unsigned)((lane*3+2)*8);
                do {
                    asm volatile("ld.volatile.shared.u64 %0, [%1];" : "=l"(kb_) : "r"(a));
                } while ((unsigned)(kb_ & 0xFFFFull) != tag);
                kbv = (unsigned)(kb_ >> 32);
            }
            myk &= ~0xFFFFull;

            unsigned selv[4], sele[4];
            #pragma unroll
            for (int r = 0; r < 4; r++) {
                unsigned hv = (unsigned)(myk >> 32);
                unsigned en = (unsigned)((myk >> 16) & 0xFFFFull);
                unsigned mv = __reduce_max_sync(0xFFFFFFFFu, hv);
                unsigned me = __reduce_max_sync(0xFFFFFFFFu, (hv == mv) ? en : 0u);
                selv[r] = mv; sele[r] = me;
                if (hv == mv && en == me) myk = 0ull;
            }
            unsigned rem = (unsigned)(myk >> 32);
            unsigned bc  = __reduce_max_sync(0xFFFFFFFFu, (rem > kbv) ? rem : kbv);

            if (lane < FCT) {
                unsigned rbase = fps_mapa(loc0, (unsigned)lane);
                #pragma unroll
                for (int r = 0; r < 4; r++) {
                    unsigned idx = 0xFFFFu - sele[r];
                    int tloc = (int)(idx & (FTOT-1)) - (int)rank * FTPB;   // owner tid (this CTA)
                    int sI   = (int)(idx >> 12);
                    float4 p = s_pts[tloc*FP + sI];                        // LDS broadcast
                    int slot = (int)rank*4 + r;
                    ull key = ((ull)selv[r] << 32) | ((ull)sele[r] << 16);
                    unsigned ak = rbase + (smem_u32_(&s_ck [buf][slot]) - loc0);
                    unsigned ax = rbase + (smem_u32_(&s_cxy[buf][slot]) - loc0);
                    unsigned az = rbase + (smem_u32_(&s_cz [buf][slot]) - loc0);
                    asm volatile("st.shared::cluster.u64 [%0], %1;" :: "r"(ax), "l"(pack2(p.x, p.y)) : "memory");
                    asm volatile("st.shared::cluster.u32 [%0], %1;" :: "r"(az), "r"(__float_as_uint(p.z)) : "memory");
                    asm volatile("st.shared::cluster.u64 [%0], %1;" :: "r"(ak), "l"(key) : "memory");
                }
                unsigned ab = rbase + (smem_u32_(&s_cb[buf][rank]) - loc0);
                asm volatile("st.shared::cluster.u32 [%0], %1;" :: "r"(ab), "r"(bc) : "memory");
                unsigned abar = rbase + (smem_u32_(&s_bar[buf]) - loc0);
                asm volatile("mbarrier.arrive.release.cluster.shared::cluster.b64 _, [%0];" :: "r"(abar) : "memory");
            }
        }

        // ---- HW-sleep wait for 16 arrivals (one from each CTA) ----
        {
            int par = buf ? ph1 : ph0;
            unsigned ba = smem_u32_(&s_bar[buf]);
            unsigned done;
            asm volatile("{\n\t.reg .pred p;\n\t"
                         "mbarrier.try_wait.parity.acquire.cluster.shared::cta.b64 p, [%1], %2;\n\t"
                         "selp.b32 %0, 1, 0, p;\n\t}"
                         : "=r"(done) : "r"(ba), "r"(par) : "memory");
            while (!done) {
                asm volatile("{\n\t.reg .pred p;\n\t"
                             "mbarrier.try_wait.parity.acquire.cluster.shared::cta.b64 p, [%1], %2, 0x989680;\n\t"
                             "selp.b32 %0, 1, 0, p;\n\t}"
                             : "=r"(done) : "r"(ba), "r"(par) : "memory");
            }
            if (buf) ph1 ^= 1; else ph0 ^= 1;
        }

        // ---- read cache + vbar ----
        unsigned bmax = 0u;
        #pragma unroll
        for (int r = 0; r < FCT; r++) { unsigned b = s_cb[buf][r]; bmax = (b > bmax) ? b : bmax; }
        float vbar = __uint_as_float(bmax);
        ull k0 = s_ck[buf][lane], k1 = s_ck[buf][lane+32];
        float p0x,p0y,p1x,p1y;
        unpack2(s_cxy[buf][lane],    p0x, p0y);  float p0z = s_cz[buf][lane];
        unpack2(s_cxy[buf][lane+32], p1x, p1y);  float p1z = s_cz[buf][lane+32];

        // ---- mini-FPS over 64 cached candidates (identical in every CTA) ----
        for (int t = 0; ; t++) {
            ull lm; unsigned slotl;
            if (k0 > k1) { lm = k0; slotl = (unsigned)lane; }
            else         { lm = k1; slotl = (unsigned)lane + 32u; }
            unsigned hv = (unsigned)(lm >> 32);
            unsigned mv = __reduce_max_sync(0xFFFFFFFFu, hv);
            unsigned cand = (hv == mv)
                ? ((((unsigned)((lm >> 16) & 0xFFFFull)) << 7) | slotl) : 0u;
            unsigned mc = __reduce_max_sync(0xFFFFFFFFu, cand);   // max enc dominates -> min idx
            float mvf = __uint_as_float(mv);
            if (t > 0 && !(mvf > vbar)) break;         // selection no longer provably global
            unsigned enc  = mc >> 7;
            unsigned slot = mc & 127u;
            if (rank == 0 && tid == 0) g_anchors[m] = (int)(0xFFFFu - enc);
            m++;
            if (m >= nA) break;

            float apx, apy; unpack2(s_cxy[buf][slot], apx, apy);
            float apz = s_cz[buf][slot];
            if (slot == (unsigned)lane)        k0 = 0ull;
            if (slot == (unsigned)lane + 32u)  k1 = 0ull;

            // cached-value updates (scalar; IEEE-identical to packed path)
            {
                float dx = p0x - apx, dy = p0y - apy, dz = p0z - apz;
                float d  = fmaf(dx, dx, fmaf(dy, dy, dz*dz));
                float nv = fminf(__uint_as_float((unsigned)(k0 >> 32)), d);
                k0 = (k0 & 0xFFFFFFFFull) | ((ull)__float_as_uint(nv) << 32);
            }
            {
                float dx = p1x - apx, dy = p1y - apy, dz = p1z - apz;
                float d  = fmaf(dx, dx, fmaf(dy, dy, dz*dz));
                float nv = fminf(__uint_as_float((unsigned)(k1 >> 32)), d);
                k1 = (k1 & 0xFFFFFFFFull) | ((ull)__float_as_uint(nv) << 32);
            }

            // md update vs this anchor (5 packed pairs)
            ull nax = pack2(-apx, -apx), nay = pack2(-apy, -apy), naz = pack2(-apz, -apz);
            #pragma unroll
            for (int p = 0; p < NPAIR; p++) {
                ull dx2 = add2_(X2[p], nax);
                ull dy2 = add2_(Y2[p], nay);
                ull dz2 = add2_(Z2[p], naz);
                ull dd  = fma2_(dx2, dx2, fma2_(dy2, dy2, mul2_(dz2, dz2)));
                float dlo, dhi; unpack2(dd, dlo, dhi);
                md[2*p]   = fminf(md[2*p],   dlo);
                md[2*p+1] = fminf(md[2*p+1], dhi);
            }
        }
    }
    cluster_sync_();
}

// ---------------- KNN + PCA + loss: one warp per TWO anchors (halved L2 traffic) ----
__device__ __forceinline__ double wsum_d(double v) {
    #pragma unroll
    for (int o = 16; o > 0; o >>= 1) v += __shfl_xor_sync(0xFFFFFFFFu, v, o);
    return v;
}

__device__ __forceinline__ void topk_merge_pca_loss(
    const float* __restrict__ vec_pred, int i, int lane,
    float* vv, int* ii
) {
    // 20-round warp merge; ties -> lower index (matches jax top_k)
    int nbr = -1;
    for (int r = 0; r < KK; r++) {
        unsigned mm = __float_as_uint(vv[0]);
        mm = (mm & 0x80000000u) ? ~mm : (mm | 0x80000000u);
        ull key = ((ull)mm << 32) | (unsigned)ii[0];
        #pragma unroll
        for (int o = 16; o > 0; o >>= 1) {
            ull k2 = __shfl_xor_sync(0xFFFFFFFFu, key, o);
            if (k2 < key) key = k2;
        }
        int widx = (int)(unsigned)key;
        if (lane == r) nbr = widx;
        if (ii[0] == widx) {
            #pragma unroll
            for (int k = 0; k < KK-1; k++) { vv[k]=vv[k+1]; ii[k]=ii[k+1]; }
            vv[KK-1] = INFF; ii[KK-1] = 0x7fffffff;
        }
    }

    // gather neighbors (lanes 0..19), covariance in double
    double x=0.0, y=0.0, z=0.0;
    if (lane < KK) { float4 q = g_p4[nbr]; x=q.x; y=q.y; z=q.z; }
    double sx = wsum_d(x), sy = wsum_d(y), sz = wsum_d(z);
    double mx = sx/KK, my = sy/KK, mz = sz/KK;
    double cx = (lane<KK) ? x-mx : 0.0;
    double cy = (lane<KK) ? y-my : 0.0;
    double cz = (lane<KK) ? z-mz : 0.0;
    double xx = wsum_d(cx*cx), xy = wsum_d(cx*cy), xz = wsum_d(cx*cz);
    double yy = wsum_d(cy*cy), yz = wsum_d(cy*cz), zz = wsum_d(cz*cz);

    if (lane == 0) {
        double A=xx, B=yy, C=zz, D=xy, E=xz, F=yz;
        double p1 = D*D + E*E + F*F;
        double q3 = (A+B+C)/3.0;
        double p2 = (A-q3)*(A-q3) + (B-q3)*(B-q3) + (C-q3)*(C-q3) + 2.0*p1;
        double p  = sqrt(p2/6.0);
        double lam;
        if (p > 0.0) {
            double ip = 1.0/p;
            double b00=(A-q3)*ip, b11=(B-q3)*ip, b22=(C-q3)*ip;
            double b01=D*ip, b02=E*ip, b12=F*ip;
            double det = b00*(b11*b22 - b12*b12)
                       - b01*(b01*b22 - b12*b02)
                       + b02*(b01*b12 - b11*b02);
            double rr = det*0.5;
            rr = fmin(1.0, fmax(-1.0, rr));
            lam = q3 + 2.0*p*cos(acos(rr)/3.0);
        } else lam = q3;

        double r0x=A-lam, r0y=D,     r0z=E;
        double r1x=D,     r1y=B-lam, r1z=F;
        double r2x=E,     r2y=F,     r2z=C-lam;
        double c1x=r0y*r1z-r0z*r1y, c1y=r0z*r1x-r0x*r1z, c1z=r0x*r1y-r0y*r1x;
        double c2x=r0y*r2z-r0z*r2y, c2y=r0z*r2x-r0x*r2z, c2z=r0x*r2y-r0y*r2x;
        double c3x=r1y*r2z-r1z*r2y, c3y=r1z*r2x-r1x*r2z, c3z=r1x*r2y-r1y*r2x;
        double n1=c1x*c1x+c1y*c1y+c1z*c1z;
        double n2=c2x*c2x+c2y*c2y+c2z*c2z;
        double n3=c3x*c3x+c3y*c3y+c3z*c3z;
        double vx=c1x, vy=c1y, vz=c1z, bn=n1;
        if (n2 > bn) { vx=c2x; vy=c2y; vz=c2z; bn=n2; }
        if (n3 > bn) { vx=c3x; vy=c3y; vz=c3z; bn=n3; }
        if (bn < 1e-300) { vx=1.0; vy=0.0; vz=0.0; bn=1.0; }
        double inv = rsqrt(bn);
        vx*=inv; vy*=inv; vz*=inv;

        const float* vp = vec_pred + 3*i;
        double ax=vp[0], ay=vp[1], az=vp[2];
        double nrm = sqrt(ax*ax + ay*ay + az*az);
        if (nrm < 1e-8) nrm = 1e-8;
        double dt = ax*vx + ay*vy + az*vz;
        double ac = fabs(dt)/nrm;
        g_terms[i] = log(ac + 1e-6);
    }
}

__global__ void knn_loss_kernel(const float* __restrict__ vec_pred, int N, int nA) {
    int wid  = threadIdx.x >> 5;
    int lane = threadIdx.x & 31;
    int gw = blockIdx.x * (blockDim.x >> 5) + wid;
    int i0 = 2*gw, i1 = 2*gw + 1;
    if (i0 >= nA) return;
    bool have1 = (i1 < nA);

    float4 ap0 = g_p4[g_anchors[i0]];
    float4 ap1 = have1 ? g_p4[g_anchors[i1]] : ap0;
    float na20 = ap0.w, na21 = ap1.w;

    float vv0[KK], vv1[KK]; int ii0[KK], ii1[KK];
    #pragma unroll
    for (int k = 0; k < KK; k++) {
        vv0[k] = INFF; ii0[k] = 0x7fffffff;
        vv1[k] = INFF; ii1[k] = 0x7fffffff;
    }

    int steps = N >> 5;
    #pragma unroll 2
    for (int s = 0; s < steps; s++) {
        int j = (s << 5) + lane;
        float4 q = g_p4[j];
        float dot0 = fmaf(ap0.z, q.z, fmaf(ap0.y, q.y, ap0.x*q.x));
        float d20 = (na20 - 2.0f*dot0) + q.w;            // reference's expansion
        if (d20 < vv0[KK-1]) {
            float cd = d20; int cj = j;
            #pragma unroll
            for (int k = 0; k < KK; k++) {
                if (cd < vv0[k]) { float tv=vv0[k]; int ti=ii0[k]; vv0[k]=cd; ii0[k]=cj; cd=tv; cj=ti; }
            }
        }
        float dot1 = fmaf(ap1.z, q.z, fmaf(ap1.y, q.y, ap1.x*q.x));
        float d21 = (na21 - 2.0f*dot1) + q.w;
        if (d21 < vv1[KK-1]) {
            float cd = d21; int cj = j;
            #pragma unroll
            for (int k = 0; k < KK; k++) {
                if (cd < vv1[k]) { float tv=vv1[k]; int ti=ii1[k]; vv1[k]=cd; ii1[k]=cj; cd=tv; cj=ti; }
            }
        }
    }
    int rem = N - (steps << 5);
    if (rem > 0 && lane < rem) {
        int j = (steps << 5) + lane;
        float4 q = g_p4[j];
        float dot0 = fmaf(ap0.z, q.z, fmaf(ap0.y, q.y, ap0.x*q.x));
        float d20 = (na20 - 2.0f*dot0) + q.w;
        if (d20 < vv0[KK-1]) {
            float cd = d20; int cj = j;
            #pragma unroll
            for (int k = 0; k < KK; k++) {
                if (cd < vv0[k]) { float tv=vv0[k]; int ti=ii0[k]; vv0[k]=cd; ii0[k]=cj; cd=tv; cj=ti; }
            }
        }
        float dot1 = fmaf(ap1.z, q.z, fmaf(ap1.y, q.y, ap1.x*q.x));
        float d21 = (na21 - 2.0f*dot1) + q.w;
        if (d21 < vv1[KK-1]) {
            float cd = d21; int cj = j;
            #pragma unroll
            for (int k = 0; k < KK; k++) {
                if (cd < vv1[k]) { float tv=vv1[k]; int ti=ii1[k]; vv1[k]=cd; ii1[k]=cj; cd=tv; cj=ti; }
            }
        }
    }

    topk_merge_pca_loss(vec_pred, i0, lane, vv0, ii0);
    if (have1) topk_merge_pca_loss(vec_pred, i1, lane, vv1, ii1);
}

// ---------------- final deterministic reduction ----------------
__global__ void reduce_kernel(int nA, float* __restrict__ out) {
    __shared__ double sm[32];
    int tid = threadIdx.x;
    double s = 0.0;
    for (int i = tid; i < nA; i += blockDim.x) s += g_terms[i];
    s = wsum_d(s);
    if ((tid & 31) == 0) sm[tid >> 5] = s;
    __syncthreads();
    if (tid < 32) {
        double v = (tid < (int)(blockDim.x >> 5)) ? sm[tid] : 0.0;
        v = wsum_d(v);
        if (tid == 0) out[0] = (float)(-v / (double)nA);
    }
}

// ---------------- launch ----------------
extern "C" void kernel_launch(void* const* d_in, const int* in_sizes, int n_in,
                              void* d_out, int out_size) {
    const float* vec_pred = (const float*)d_in[0];
    const float* pos      = (const float*)d_in[1];
    int N  = in_sizes[1] / 3;
    int nA = (int)ceil(0.1 * (double)N);

    int smem = FTPB * FP * (int)sizeof(float4);   // 40 KB point mirror
    cudaFuncSetAttribute(fps_kernel, cudaFuncAttributeMaxDynamicSharedMemorySize, smem);
    cudaFuncSetAttribute(fps_kernel, cudaFuncAttributeNonPortableClusterSizeAllowed, 1);

    prep_kernel<<<(N + 255)/256, 256>>>(pos, N);

    cudaLaunchConfig_t cfg = {};
    cfg.gridDim  = dim3(FCT, 1, 1);
    cfg.blockDim = dim3(FTPB, 1, 1);
    cfg.dynamicSmemBytes = (size_t)smem;
    cfg.stream = 0;                                // legacy default stream (capture-consistent)
    cudaLaunchAttribute attrs[1];
    attrs[0].id = cudaLaunchAttributeClusterDimension;
    attrs[0].val.clusterDim.x = FCT;
    attrs[0].val.clusterDim.y = 1;
    attrs[0].val.clusterDim.z = 1;
    cfg.attrs = attrs;
    cfg.numAttrs = 1;
    cudaLaunchKernelEx(&cfg, fps_kernel, N, nA);

    int wpb = 8;                                   // 8 warps/CTA, 2 anchors/warp
    int npairs = (nA + 1) / 2;
    knn_loss_kernel<<<(npairs + wpb - 1)/wpb, 32*wpb>>>(vec_pred, N, nA);
    reduce_kernel<<<1, 512>>>(nA, (float*)d_out);
}

// round 16
// speedup vs baseline: 1.1869x; 1.1869x over previous
#include <cuda_runtime.h>
#include <cstdint>
#include <math.h>

// ---------------- problem-scale device scratch (static, no allocation) ----------------
#define NMAX 40960
__device__ float4 g_p4[NMAX];      // x, y, z, |p|^2
__device__ int    g_anchors[8192];
__device__ double g_terms[8192];

#define KK 20
#define INFF __int_as_float(0x7f800000)
typedef unsigned long long ull;

// ---------------- prep: SoA float4 with precomputed |p|^2 ----------------
__global__ void prep_kernel(const float* __restrict__ pos, int N) {
    int j = blockIdx.x * blockDim.x + threadIdx.x;
    if (j < N) {
        float x = pos[3*j], y = pos[3*j+1], z = pos[3*j+2];
        float n2 = __fadd_rn(__fadd_rn(__fmul_rn(x,x), __fmul_rn(y,y)), __fmul_rn(z,z));
        g_p4[j] = make_float4(x, y, z, n2);
    }
}

// ---------------- FPS: 16-CTA cluster, 256 thr/CTA; batched candidate-cache --------
#define FCT  16
#define FTPB 256
#define NW   (FTPB/32)    // 8 warps
#define FTOT (FCT*FTPB)   // 4096 threads
#define FP   10           // ceil(40000/4096)
#define NPAIR (FP/2)
#define IMAXI 0x7fffffff

__device__ __forceinline__ unsigned fps_mapa(unsigned addr, unsigned rank) {
    unsigned r;
    asm("mapa.shared::cluster.u32 %0, %1, %2;" : "=r"(r) : "r"(addr), "r"(rank));
    return r;
}
__device__ __forceinline__ unsigned smem_u32_(const void* p) {
    return (unsigned)__cvta_generic_to_shared(p);
}
__device__ __forceinline__ void cluster_sync_() {
    asm volatile("barrier.cluster.arrive.aligned;\n\tbarrier.cluster.wait.aligned;" ::: "memory");
}
__device__ __forceinline__ ull pack2(float lo, float hi) {
    ull v; asm("mov.b64 %0, {%1, %2};" : "=l"(v) : "r"(__float_as_uint(lo)), "r"(__float_as_uint(hi)));
    return v;
}
__device__ __forceinline__ void unpack2(ull v, float &lo, float &hi) {
    unsigned a, b; asm("mov.b64 {%0, %1}, %2;" : "=r"(a), "=r"(b) : "l"(v));
    lo = __uint_as_float(a); hi = __uint_as_float(b);
}
__device__ __forceinline__ ull add2_(ull a, ull b) {
    ull d; asm("add.rn.f32x2 %0, %1, %2;" : "=l"(d) : "l"(a), "l"(b)); return d;
}
__device__ __forceinline__ ull mul2_(ull a, ull b) {
    ull d; asm("mul.rn.f32x2 %0, %1, %2;" : "=l"(d) : "l"(a), "l"(b)); return d;
}
__device__ __forceinline__ ull fma2_(ull a, ull b, ull c) {
    ull d; asm("fma.rn.f32x2 %0, %1, %2, %3;" : "=l"(d) : "l"(a), "l"(b), "l"(c)); return d;
}

__global__ void __launch_bounds__(FTPB,1)
fps_kernel(int N, int nA) {
    extern __shared__ float4 s_pts[];          // [FTPB*FP] point mirror (40 KB)
    __shared__ ull      s_wkey[NW*4];          // per-warp: k1,k2,k3,kb  (tagged)
    __shared__ ull      s_ck  [2][64];         // cache keys: val32|enc16|0  (16 CTAs x 4)
    __shared__ ull      s_cxy [2][64];         // cache positions x,y
    __shared__ float    s_cz  [2][64];         // cache positions z
    __shared__ unsigned s_cb  [2][FCT];        // per-CTA bounds
    __shared__ ull      s_bar [2];             // mbarriers (count = FCT)

    int tid  = threadIdx.x;
    unsigned rank; asm("mov.u32 %0, %%cluster_ctarank;" : "=r"(rank));
    int gt   = (int)rank * FTPB + tid;
    int lane = tid & 31, wid = tid >> 5;

    if (tid == 0) {
        asm volatile("mbarrier.init.shared.b64 [%0], %1;" :: "r"(smem_u32_(&s_bar[0])), "r"(FCT) : "memory");
        asm volatile("mbarrier.init.shared.b64 [%0], %1;" :: "r"(smem_u32_(&s_bar[1])), "r"(FCT) : "memory");
    }
    if (tid < NW*4) s_wkey[tid] = 0ull;        // tag 0 != first batch tag 1

    // register-resident points (5 packed pairs) + min-distance array
    ull X2[NPAIR], Y2[NPAIR], Z2[NPAIR];
    float md[FP];
    bool has10 = (9*FTOT + gt) < N;

    float4 a0 = g_p4[0];
    float xs[FP], ys[FP], zs[FP];
    #pragma unroll
    for (int s = 0; s < FP; s++) {
        int gi = s*FTOT + gt;                  // < NMAX; pad reads zero-init tail
        float4 q = g_p4[gi];
        s_pts[tid*FP + s] = q;
        xs[s]=q.x; ys[s]=q.y; zs[s]=q.z;
        float dx=q.x-a0.x, dy=q.y-a0.y, dz=q.z-a0.z;
        float d = fmaf(dx,dx, fmaf(dy,dy, dz*dz));
        bool valid = (s < 9) || has10;
        md[s] = valid ? d : -1.0f;
    }
    #pragma unroll
    for (int p = 0; p < NPAIR; p++) {
        X2[p] = pack2(xs[2*p], xs[2*p+1]);
        Y2[p] = pack2(ys[2*p], ys[2*p+1]);
        Z2[p] = pack2(zs[2*p], zs[2*p+1]);
    }
    if (rank == 0 && tid == 0) g_anchors[0] = 0;
    __syncthreads();      // s_pts, s_wkey, bars ready (CTA-local)
    cluster_sync_();      // visible cluster-wide before any remote store

    unsigned wkbase = smem_u32_(&s_wkey[0]);
    unsigned loc0   = smem_u32_(&s_ck[0][0]);
    int ph0 = 0, ph1 = 0;
    int m = 1;
    unsigned eb = 0;

    while (m < nA) {
        eb++;
        int buf = (int)(eb & 1u);
        unsigned tag = eb & 0xFFFFu;

        // ---- warp top-3 + 4th-value bound (exact, removal-based) ----
        {
            float tv[FP];
            #pragma unroll
            for (int s = 0; s < FP; s++) tv[s] = md[s];
            unsigned selv[3], sele[3];
            #pragma unroll
            for (int r = 0; r < 3; r++) {
                float bvv = tv[0]; int bs = 0;
                #pragma unroll
                for (int s = 1; s < FP; s++) if (tv[s] > bvv) { bvv = tv[s]; bs = s; }
                unsigned vb = __float_as_uint(fmaxf(bvv, 0.0f));   // valid slots >= 0
                unsigned wv = __reduce_max_sync(0xFFFFFFFFu, vb);
                unsigned en = 0xFFFFu - (unsigned)(gt + bs*FTOT);
                unsigned we = __reduce_max_sync(0xFFFFFFFFu, (vb == wv) ? en : 0u);
                selv[r] = wv; sele[r] = we;
                bool won = (vb == wv) && (en == we);
                #pragma unroll
                for (int s = 0; s < FP; s++) if (won && s == bs) tv[s] = -1.0f;
            }
            float rv = tv[0];
            #pragma unroll
            for (int s = 1; s < FP; s++) rv = fmaxf(rv, tv[s]);
            unsigned w4 = __reduce_max_sync(0xFFFFFFFFu, __float_as_uint(fmaxf(rv, 0.0f)));
            // lanes 0..3 post keys k1,k2,k3,bound in parallel (values warp-uniform)
            if (lane < 4) {
                ull kk;
                if (lane == 0)      kk = ((ull)selv[0] << 32) | ((ull)sele[0] << 16) | (ull)tag;
                else if (lane == 1) kk = ((ull)selv[1] << 32) | ((ull)sele[1] << 16) | (ull)tag;
                else if (lane == 2) kk = ((ull)selv[2] << 32) | ((ull)sele[2] << 16) | (ull)tag;
                else                kk = ((ull)w4      << 32) | (ull)tag;
                asm volatile("st.volatile.shared.u64 [%0], %1;" :: "r"(wkbase + (unsigned)((wid*4+lane)*8)), "l"(kk) : "memory");
            }
        }

        // ---- warp0: CTA top-4 of 24 warp keys + bound, ship to all 16 CTAs ----
        if (wid == 0) {
            ull myk = 0ull;
            if (lane < 3*NW) {                 // 24 keys: warp w=lane/3, key c=lane%3
                int w = lane / 3, c = lane - 3*w;
                unsigned a = wkbase + (unsigned)((w*4 + c)*8);
                do {
                    asm volatile("ld.volatile.shared.u64 %0, [%1];" : "=l"(myk) : "r"(a));
                } while ((unsigned)(myk & 0xFFFFull) != tag);
            }
            unsigned kbv = 0u;
            if (lane < NW) {
                ull kb_;
                unsigned a = wkbase + (unsigned)((lane*4+3)*8);
                do {
                    asm volatile("ld.volatile.shared.u64 %0, [%1];" : "=l"(kb_) : "r"(a));
                } while ((unsigned)(kb_ & 0xFFFFull) != tag);
                kbv = (unsigned)(kb_ >> 32);
            }
            myk &= ~0xFFFFull;

            unsigned selv[4], sele[4];
            #pragma unroll
            for (int r = 0; r < 4; r++) {
                unsigned hv = (unsigned)(myk >> 32);
                unsigned en = (unsigned)((myk >> 16) & 0xFFFFull);
                unsigned mv = __reduce_max_sync(0xFFFFFFFFu, hv);
                unsigned me = __reduce_max_sync(0xFFFFFFFFu, (hv == mv) ? en : 0u);
                selv[r] = mv; sele[r] = me;
                if (hv == mv && en == me) myk = 0ull;
            }
            unsigned rem = (unsigned)(myk >> 32);
            unsigned bc  = __reduce_max_sync(0xFFFFFFFFu, (rem > kbv) ? rem : kbv);

            if (lane < FCT) {
                unsigned rbase = fps_mapa(loc0, (unsigned)lane);
                #pragma unroll
                for (int r = 0; r < 4; r++) {
                    unsigned idx = 0xFFFFu - sele[r];
                    int tloc = (int)(idx & (FTOT-1)) - (int)rank * FTPB;   // owner tid (this CTA)
                    int sI   = (int)(idx >> 12);
                    float4 p = s_pts[tloc*FP + sI];                        // LDS broadcast
                    int slot = (int)rank*4 + r;
                    ull key = ((ull)selv[r] << 32) | ((ull)sele[r] << 16);
                    unsigned ak = rbase + (smem_u32_(&s_ck [buf][slot]) - loc0);
                    unsigned ax = rbase + (smem_u32_(&s_cxy[buf][slot]) - loc0);
                    unsigned az = rbase + (smem_u32_(&s_cz [buf][slot]) - loc0);
                    asm volatile("st.shared::cluster.u64 [%0], %1;" :: "r"(ax), "l"(pack2(p.x, p.y)) : "memory");
                    asm volatile("st.shared::cluster.u32 [%0], %1;" :: "r"(az), "r"(__float_as_uint(p.z)) : "memory");
                    asm volatile("st.shared::cluster.u64 [%0], %1;" :: "r"(ak), "l"(key) : "memory");
                }
                unsigned ab = rbase + (smem_u32_(&s_cb[buf][rank]) - loc0);
                asm volatile("st.shared::cluster.u32 [%0], %1;" :: "r"(ab), "r"(bc) : "memory");
                unsigned abar = rbase + (smem_u32_(&s_bar[buf]) - loc0);
                asm volatile("mbarrier.arrive.release.cluster.shared::cluster.b64 _, [%0];" :: "r"(abar) : "memory");
            }
        }

        // ---- HW-sleep wait for 16 arrivals (one from each CTA) ----
        {
            int par = buf ? ph1 : ph0;
            unsigned ba = smem_u32_(&s_bar[buf]);
            unsigned done;
            asm volatile("{\n\t.reg .pred p;\n\t"
                         "mbarrier.try_wait.parity.acquire.cluster.shared::cta.b64 p, [%1], %2;\n\t"
                         "selp.b32 %0, 1, 0, p;\n\t}"
                         : "=r"(done) : "r"(ba), "r"(par) : "memory");
            while (!done) {
                asm volatile("{\n\t.reg .pred p;\n\t"
                             "mbarrier.try_wait.parity.acquire.cluster.shared::cta.b64 p, [%1], %2, 0x989680;\n\t"
                             "selp.b32 %0, 1, 0, p;\n\t}"
                             : "=r"(done) : "r"(ba), "r"(par) : "memory");
            }
            if (buf) ph1 ^= 1; else ph0 ^= 1;
        }

        // ---- read cache + vbar ----
        unsigned bmax = 0u;
        #pragma unroll
        for (int r = 0; r < FCT; r++) { unsigned b = s_cb[buf][r]; bmax = (b > bmax) ? b : bmax; }
        float vbar = __uint_as_float(bmax);
        ull k0 = s_ck[buf][lane], k1 = s_ck[buf][lane+32];
        float p0x,p0y,p1x,p1y;
        unpack2(s_cxy[buf][lane],    p0x, p0y);  float p0z = s_cz[buf][lane];
        unpack2(s_cxy[buf][lane+32], p1x, p1y);  float p1z = s_cz[buf][lane+32];

        // ---- mini-FPS over 64 cached candidates (identical in every CTA) ----
        for (int t = 0; ; t++) {
            ull lm; unsigned slotl;
            if (k0 > k1) { lm = k0; slotl = (unsigned)lane; }
            else         { lm = k1; slotl = (unsigned)lane + 32u; }
            unsigned hv = (unsigned)(lm >> 32);
            unsigned mv = __reduce_max_sync(0xFFFFFFFFu, hv);
            unsigned cand = (hv == mv)
                ? ((((unsigned)((lm >> 16) & 0xFFFFull)) << 7) | slotl) : 0u;
            unsigned mc = __reduce_max_sync(0xFFFFFFFFu, cand);   // max enc dominates -> min idx
            float mvf = __uint_as_float(mv);
            if (t > 0 && !(mvf > vbar)) break;         // selection no longer provably global
            unsigned enc  = mc >> 7;
            unsigned slot = mc & 127u;
            if (rank == 0 && tid == 0) g_anchors[m] = (int)(0xFFFFu - enc);
            m++;
            if (m >= nA) break;

            float apx, apy; unpack2(s_cxy[buf][slot], apx, apy);
            float apz = s_cz[buf][slot];
            if (slot == (unsigned)lane)        k0 = 0ull;
            if (slot == (unsigned)lane + 32u)  k1 = 0ull;

            // cached-value updates (scalar; IEEE-identical to packed path)
            {
                float dx = p0x - apx, dy = p0y - apy, dz = p0z - apz;
                float d  = fmaf(dx, dx, fmaf(dy, dy, dz*dz));
                float nv = fminf(__uint_as_float((unsigned)(k0 >> 32)), d);
                k0 = (k0 & 0xFFFFFFFFull) | ((ull)__float_as_uint(nv) << 32);
            }
            {
                float dx = p1x - apx, dy = p1y - apy, dz = p1z - apz;
                float d  = fmaf(dx, dx, fmaf(dy, dy, dz*dz));
                float nv = fminf(__uint_as_float((unsigned)(k1 >> 32)), d);
                k1 = (k1 & 0xFFFFFFFFull) | ((ull)__float_as_uint(nv) << 32);
            }

            // md update vs this anchor (5 packed pairs)
            ull nax = pack2(-apx, -apx), nay = pack2(-apy, -apy), naz = pack2(-apz, -apz);
            #pragma unroll
            for (int p = 0; p < NPAIR; p++) {
                ull dx2 = add2_(X2[p], nax);
                ull dy2 = add2_(Y2[p], nay);
                ull dz2 = add2_(Z2[p], naz);
                ull dd  = fma2_(dx2, dx2, fma2_(dy2, dy2, mul2_(dz2, dz2)));
                float dlo, dhi; unpack2(dd, dlo, dhi);
                md[2*p]   = fminf(md[2*p],   dlo);
                md[2*p+1] = fminf(md[2*p+1], dhi);
            }
        }
    }
    cluster_sync_();
}

// ---------------- KNN + PCA + per-anchor loss term: one warp per anchor ----------------
__device__ __forceinline__ double wsum_d(double v) {
    #pragma unroll
    for (int o = 16; o > 0; o >>= 1) v += __shfl_xor_sync(0xFFFFFFFFu, v, o);
    return v;
}

__global__ void knn_loss_kernel(const float* __restrict__ vec_pred, int N, int nA) {
    int wid  = threadIdx.x >> 5;
    int lane = threadIdx.x & 31;
    int i = blockIdx.x * (blockDim.x >> 5) + wid;
    if (i >= nA) return;

    int a = g_anchors[i];
    float4 ap = g_p4[a];
    float na2 = ap.w;

    float vv[KK]; int ii[KK];
    #pragma unroll
    for (int k = 0; k < KK; k++) { vv[k] = INFF; ii[k] = 0x7fffffff; }

    int steps = N >> 5;
    #pragma unroll 4
    for (int s = 0; s < steps; s++) {
        int j = (s << 5) + lane;
        float4 q = g_p4[j];
        float dot = fmaf(ap.z, q.z, fmaf(ap.y, q.y, ap.x*q.x));
        float d2 = (na2 - 2.0f*dot) + q.w;               // reference's expansion
        if (d2 < vv[KK-1]) {
            float cd = d2; int cj = j;
            #pragma unroll
            for (int k = 0; k < KK; k++) {
                if (cd < vv[k]) { float tv=vv[k]; int ti=ii[k]; vv[k]=cd; ii[k]=cj; cd=tv; cj=ti; }
            }
        }
    }
    int rem = N - (steps << 5);
    if (rem > 0 && lane < rem) {
        int j = (steps << 5) + lane;
        float4 q = g_p4[j];
        float dot = fmaf(ap.z, q.z, fmaf(ap.y, q.y, ap.x*q.x));
        float d2 = (na2 - 2.0f*dot) + q.w;
        if (d2 < vv[KK-1]) {
            float cd = d2; int cj = j;
            #pragma unroll
            for (int k = 0; k < KK; k++) {
                if (cd < vv[k]) { float tv=vv[k]; int ti=ii[k]; vv[k]=cd; ii[k]=cj; cd=tv; cj=ti; }
            }
        }
    }

    // 20-round warp merge; ties -> lower index (matches jax top_k)
    int nbr = -1;
    for (int r = 0; r < KK; r++) {
        unsigned mm = __float_as_uint(vv[0]);
        mm = (mm & 0x80000000u) ? ~mm : (mm | 0x80000000u);
        ull key = ((ull)mm << 32) | (unsigned)ii[0];
        #pragma unroll
        for (int o = 16; o > 0; o >>= 1) {
            ull k2 = __shfl_xor_sync(0xFFFFFFFFu, key, o);
            if (k2 < key) key = k2;
        }
        int widx = (int)(unsigned)key;
        if (lane == r) nbr = widx;
        if (ii[0] == widx) {
            #pragma unroll
            for (int k = 0; k < KK-1; k++) { vv[k]=vv[k+1]; ii[k]=ii[k+1]; }
            vv[KK-1] = INFF; ii[KK-1] = 0x7fffffff;
        }
    }

    // gather neighbors (lanes 0..19), covariance in double
    double x=0.0, y=0.0, z=0.0;
    if (lane < KK) { float4 q = g_p4[nbr]; x=q.x; y=q.y; z=q.z; }
    double sx = wsum_d(x), sy = wsum_d(y), sz = wsum_d(z);
    double mx = sx/KK, my = sy/KK, mz = sz/KK;
    double cx = (lane<KK) ? x-mx : 0.0;
    double cy = (lane<KK) ? y-my : 0.0;
    double cz = (lane<KK) ? z-mz : 0.0;
    double xx = wsum_d(cx*cx), xy = wsum_d(cx*cy), xz = wsum_d(cx*cz);
    double yy = wsum_d(cy*cy), yz = wsum_d(cy*cz), zz = wsum_d(cz*cz);

    if (lane == 0) {
        double A=xx, B=yy, C=zz, D=xy, E=xz, F=yz;
        double p1 = D*D + E*E + F*F;
        double q3 = (A+B+C)/3.0;
        double p2 = (A-q3)*(A-q3) + (B-q3)*(B-q3) + (C-q3)*(C-q3) + 2.0*p1;
        double p  = sqrt(p2/6.0);
        double lam;
        if (p > 0.0) {
            double ip = 1.0/p;
            double b00=(A-q3)*ip, b11=(B-q3)*ip, b22=(C-q3)*ip;
            double b01=D*ip, b02=E*ip, b12=F*ip;
            double det = b00*(b11*b22 - b12*b12)
                       - b01*(b01*b22 - b12*b02)
                       + b02*(b01*b12 - b11*b02);
            double rr = det*0.5;
            rr = fmin(1.0, fmax(-1.0, rr));
            lam = q3 + 2.0*p*cos(acos(rr)/3.0);
        } else lam = q3;

        double r0x=A-lam, r0y=D,     r0z=E;
        double r1x=D,     r1y=B-lam, r1z=F;
        double r2x=E,     r2y=F,     r2z=C-lam;
        double c1x=r0y*r1z-r0z*r1y, c1y=r0z*r1x-r0x*r1z, c1z=r0x*r1y-r0y*r1x;
        double c2x=r0y*r2z-r0z*r2y, c2y=r0z*r2x-r0x*r2z, c2z=r0x*r2y-r0y*r2x;
        double c3x=r1y*r2z-r1z*r2y, c3y=r1z*r2x-r1x*r2z, c3z=r1x*r2y-r1y*r2x;
        double n1=c1x*c1x+c1y*c1y+c1z*c1z;
        double n2=c2x*c2x+c2y*c2y+c2z*c2z;
        double n3=c3x*c3x+c3y*c3y+c3z*c3z;
        double vx=c1x, vy=c1y, vz=c1z, bn=n1;
        if (n2 > bn) { vx=c2x; vy=c2y; vz=c2z; bn=n2; }
        if (n3 > bn) { vx=c3x; vy=c3y; vz=c3z; bn=n3; }
        if (bn < 1e-300) { vx=1.0; vy=0.0; vz=0.0; bn=1.0; }
        double inv = rsqrt(bn);
        vx*=inv; vy*=inv; vz*=inv;

        const float* vp = vec_pred + 3*i;
        double ax=vp[0], ay=vp[1], az=vp[2];
        double nrm = sqrt(ax*ax + ay*ay + az*az);
        if (nrm < 1e-8) nrm = 1e-8;
        double dt = ax*vx + ay*vy + az*vz;
        double ac = fabs(dt)/nrm;
        g_terms[i] = log(ac + 1e-6);
    }
}

// ---------------- final deterministic reduction ----------------
__global__ void reduce_kernel(int nA, float* __restrict__ out) {
    __shared__ double sm[32];
    int tid = threadIdx.x;
    double s = 0.0;
    for (int i = tid; i < nA; i += blockDim.x) s += g_terms[i];
    s = wsum_d(s);
    if ((tid & 31) == 0) sm[tid >> 5] = s;
    __syncthreads();
    if (tid < 32) {
        double v = (tid < (int)(blockDim.x >> 5)) ? sm[tid] : 0.0;
        v = wsum_d(v);
        if (tid == 0) out[0] = (float)(-v / (double)nA);
    }
}

// ---------------- launch ----------------
extern "C" void kernel_launch(void* const* d_in, const int* in_sizes, int n_in,
                              void* d_out, int out_size) {
    const float* vec_pred = (const float*)d_in[0];
    const float* pos      = (const float*)d_in[1];
    int N  = in_sizes[1] / 3;
    int nA = (int)ceil(0.1 * (double)N);

    int smem = FTPB * FP * (int)sizeof(float4);   // 40 KB point mirror
    cudaFuncSetAttribute(fps_kernel, cudaFuncAttributeMaxDynamicSharedMemorySize, smem);
    cudaFuncSetAttribute(fps_kernel, cudaFuncAttributeNonPortableClusterSizeAllowed, 1);

    prep_kernel<<<(N + 255)/256, 256>>>(pos, N);

    cudaLaunchConfig_t cfg = {};
    cfg.gridDim  = dim3(FCT, 1, 1);
    cfg.blockDim = dim3(FTPB, 1, 1);
    cfg.dynamicSmemBytes = (size_t)smem;
    cfg.stream = 0;                                // legacy default stream (capture-consistent)
    cudaLaunchAttribute attrs[1];
    attrs[0].id = cudaLaunchAttributeClusterDimension;
    attrs[0].val.clusterDim.x = FCT;
    attrs[0].val.clusterDim.y = 1;
    attrs[0].val.clusterDim.z = 1;
    cfg.attrs = attrs;
    cfg.numAttrs = 1;
    cudaLaunchKernelEx(&cfg, fps_kernel, N, nA);

    int wpb = 8;
    knn_loss_kernel<<<(nA + wpb - 1)/wpb, 32*wpb>>>(vec_pred, N, nA);
    reduce_kernel<<<1, 512>>>(nA, (float*)d_out);
}